// round 1
// baseline (speedup 1.0000x reference)
#include <cuda_runtime.h>

#define BQ 4096
#define NS 8192
#define DD 256
#define BM 32
#define BN 32
#define XST 260          // padded row stride (floats): 1040B, 16B aligned, 2-way-max bank pattern
#define PST 48           // P tile stride: rows 16 apart land 16 banks apart -> conflict-free writes
#define NTHREADS 256
#define NTILES (NS / BN)
#define SMEM_BYTES ((BM * XST + BN * XST + BM * PST + 6 * BM) * 4)

__device__ float g_s2half[NS];

static __device__ __forceinline__ unsigned long long ffma2(unsigned long long a,
                                                           unsigned long long b,
                                                           unsigned long long c) {
    unsigned long long d;
    asm("fma.rn.f32x2 %0, %1, %2, %3;" : "=l"(d) : "l"(a), "l"(b), "l"(c));
    return d;
}
static __device__ __forceinline__ unsigned long long fmul2(unsigned long long a,
                                                           unsigned long long b) {
    unsigned long long d;
    asm("mul.rn.f32x2 %0, %1, %2;" : "=l"(d) : "l"(a), "l"(b));
    return d;
}
static __device__ __forceinline__ unsigned long long pk2(float lo, float hi) {
    unsigned long long r;
    asm("mov.b64 %0, {%1, %2};" : "=l"(r) : "f"(lo), "f"(hi));
    return r;
}
static __device__ __forceinline__ float lo2(unsigned long long v) {
    return __uint_as_float((unsigned)v);
}
static __device__ __forceinline__ float hi2(unsigned long long v) {
    return __uint_as_float((unsigned)(v >> 32));
}

// 0.5 * ||s_n||^2, one warp per sample
__global__ void s2_kernel(const float* __restrict__ samples) {
    int w = (blockIdx.x * blockDim.x + threadIdx.x) >> 5;
    int lane = threadIdx.x & 31;
    if (w >= NS) return;
    const float* row = samples + (size_t)w * DD;
    float s = 0.f;
    #pragma unroll
    for (int i = 0; i < DD / 32; i++) {
        float v = row[lane + 32 * i];
        s = fmaf(v, v, s);
    }
    #pragma unroll
    for (int o = 16; o; o >>= 1) s += __shfl_xor_sync(0xffffffffu, s, o);
    if (lane == 0) g_s2half[w] = 0.5f * s;
}

__global__ __launch_bounds__(NTHREADS, 1) void score_kernel(
    const float* __restrict__ tvec, const float* __restrict__ x,
    const float* __restrict__ samples, float* __restrict__ out) {
    extern __shared__ float smem[];
    float* sX = smem;                 // BM x XST
    float* sK = sX + BM * XST;        // BN x XST
    float* sP = sK + BN * XST;        // BM x PST
    float* sTs = sP + BM * PST;
    float* sInvd = sTs + BM;
    float* sM = sInvd + BM;
    float* sL = sM + BM;
    float* sAl = sL + BM;
    float* sS2 = sAl + BM;

    const int tid = threadIdx.x;
    const int qbase = blockIdx.x * BM;

    // Load X tile (32 x 256, padded stride)
    #pragma unroll
    for (int r = 0; r < (BM * DD / 4) / NTHREADS; r++) {
        int idx = tid + NTHREADS * r;
        int row = idx >> 6, c4 = idx & 63;
        float4 v = *(const float4*)(x + (size_t)(qbase + row) * DD + c4 * 4);
        *(float4*)(sX + row * XST + c4 * 4) = v;
    }
    if (tid < BM) {
        float tt = tvec[qbase + tid];
        // sigma(t) = 0.01 * 10000^t ; denom = sigma^2 + 1e-8
        float ts = 0.01f * exp2f(tt * 13.287712379549449f);
        float dn = fmaf(ts, ts, 1e-8f);
        sTs[tid] = ts;
        sInvd[tid] = 1.0f / dn;
        sM[tid] = __int_as_float(0xff800000);  // -inf
        sL[tid] = 0.0f;
    }

    const int qi = tid >> 4;  // 0..15  (GEMM1: rows qi, qi+16)
    const int ni = tid & 15;  //        (GEMM1: cols ni, ni+16)
    const int q2 = tid >> 3;  // 0..31  (GEMM2: query row)
    const int cc = tid & 7;   //        (GEMM2: d-chunk)

    unsigned long long O2[16];  // 32 packed fp32 output accumulators
    #pragma unroll
    for (int j = 0; j < 16; j++) O2[j] = 0ull;

    for (int kt = 0; kt < NTILES; kt++) {
        const int nbase = kt * BN;
        // Load K tile
        #pragma unroll
        for (int r = 0; r < (BN * DD / 4) / NTHREADS; r++) {
            int idx = tid + NTHREADS * r;
            int row = idx >> 6, c4 = idx & 63;
            float4 v = *(const float4*)(samples + (size_t)(nbase + row) * DD + c4 * 4);
            *(float4*)(sK + row * XST + c4 * 4) = v;
        }
        if (tid < BN) sS2[tid] = g_s2half[nbase + tid];
        __syncthreads();

        // ---- GEMM1: S[32][32] = X @ K^T, packed f32x2, 2x2 micro-tile ----
        unsigned long long a00 = 0, a01 = 0, a02 = 0, a03 = 0;
        unsigned long long a04 = 0, a05 = 0, a06 = 0, a07 = 0;
        {
            const ulonglong2* Xr0 = (const ulonglong2*)(sX + qi * XST);
            const ulonglong2* Xr1 = (const ulonglong2*)(sX + (qi + 16) * XST);
            const ulonglong2* Kr0 = (const ulonglong2*)(sK + ni * XST);
            const ulonglong2* Kr1 = (const ulonglong2*)(sK + (ni + 16) * XST);
            #pragma unroll 8
            for (int g = 0; g < DD / 4; g++) {
                ulonglong2 av0 = Xr0[g], av1 = Xr1[g];
                ulonglong2 bv0 = Kr0[g], bv1 = Kr1[g];
                a00 = ffma2(av0.x, bv0.x, a00);
                a01 = ffma2(av0.y, bv0.y, a01);
                a02 = ffma2(av0.x, bv1.x, a02);
                a03 = ffma2(av0.y, bv1.y, a03);
                a04 = ffma2(av1.x, bv0.x, a04);
                a05 = ffma2(av1.y, bv0.y, a05);
                a06 = ffma2(av1.x, bv1.x, a06);
                a07 = ffma2(av1.y, bv1.y, a07);
            }
        }
        float s00 = (lo2(a00) + hi2(a00)) + (lo2(a01) + hi2(a01));
        float s01 = (lo2(a02) + hi2(a02)) + (lo2(a03) + hi2(a03));
        float s10 = (lo2(a04) + hi2(a04)) + (lo2(a05) + hi2(a05));
        float s11 = (lo2(a06) + hi2(a06)) + (lo2(a07) + hi2(a07));

        // ---- online softmax ----
        float invd0 = sInvd[qi], invd1 = sInvd[qi + 16];
        float s2a = sS2[ni], s2b = sS2[ni + 16];
        float l00 = (s00 - s2a) * invd0, l01 = (s01 - s2b) * invd0;
        float l10 = (s10 - s2a) * invd1, l11 = (s11 - s2b) * invd1;

        float r0 = fmaxf(l00, l01), r1 = fmaxf(l10, l11);
        #pragma unroll
        for (int o = 8; o; o >>= 1) {
            r0 = fmaxf(r0, __shfl_xor_sync(0xffffffffu, r0, o));
            r1 = fmaxf(r1, __shfl_xor_sync(0xffffffffu, r1, o));
        }
        float old0 = sM[qi], old1 = sM[qi + 16];
        float m0 = fmaxf(old0, r0), m1 = fmaxf(old1, r1);
        float p00 = __expf(l00 - m0), p01 = __expf(l01 - m0);
        float p10 = __expf(l10 - m1), p11 = __expf(l11 - m1);
        float rs0 = p00 + p01, rs1 = p10 + p11;
        #pragma unroll
        for (int o = 8; o; o >>= 1) {
            rs0 += __shfl_xor_sync(0xffffffffu, rs0, o);
            rs1 += __shfl_xor_sync(0xffffffffu, rs1, o);
        }
        sP[qi * PST + ni] = p00;
        sP[qi * PST + ni + 16] = p01;
        sP[(qi + 16) * PST + ni] = p10;
        sP[(qi + 16) * PST + ni + 16] = p11;
        if (ni == 0) {
            float al0 = __expf(old0 - m0), al1 = __expf(old1 - m1);
            sAl[qi] = al0;
            sAl[qi + 16] = al1;
            sM[qi] = m0;
            sM[qi + 16] = m1;
            sL[qi] = sL[qi] * al0 + rs0;
            sL[qi + 16] = sL[qi + 16] * al1 + rs1;
        }
        __syncthreads();

        // ---- GEMM2: O += P @ K ----
        {
            float alpha = sAl[q2];
            if (alpha != 1.0f) {
                unsigned long long al2 = pk2(alpha, alpha);
                #pragma unroll
                for (int j = 0; j < 16; j++) O2[j] = fmul2(O2[j], al2);
            }
            const float* Pr = sP + q2 * PST;
            #pragma unroll 4
            for (int k = 0; k < BN; k++) {
                float p = Pr[k];
                unsigned long long p2 = pk2(p, p);
                const ulonglong2* Kr = (const ulonglong2*)(sK + k * XST) + cc;
                #pragma unroll
                for (int i = 0; i < 8; i++) {
                    ulonglong2 kv = Kr[8 * i];
                    O2[2 * i] = ffma2(p2, kv.x, O2[2 * i]);
                    O2[2 * i + 1] = ffma2(p2, kv.y, O2[2 * i + 1]);
                }
            }
        }
        __syncthreads();
    }

    // ---- epilogue: out = t_scale * (O/l - x) * inv_denom ----
    float linv = 1.0f / sL[q2];
    float scale = sTs[q2] * sInvd[q2];
    float* orow = out + (size_t)(qbase + q2) * DD;
    const float* xrow = sX + q2 * XST;
    #pragma unroll
    for (int i = 0; i < 8; i++) {
        int d0 = cc * 4 + 32 * i;
        float4 o;
        o.x = (lo2(O2[2 * i]) * linv - xrow[d0 + 0]) * scale;
        o.y = (hi2(O2[2 * i]) * linv - xrow[d0 + 1]) * scale;
        o.z = (lo2(O2[2 * i + 1]) * linv - xrow[d0 + 2]) * scale;
        o.w = (hi2(O2[2 * i + 1]) * linv - xrow[d0 + 3]) * scale;
        *(float4*)(orow + d0) = o;
    }
}

extern "C" void kernel_launch(void* const* d_in, const int* in_sizes, int n_in,
                              void* d_out, int out_size) {
    const float* t = nullptr;
    const float* x = nullptr;
    const float* s = nullptr;
    for (int i = 0; i < n_in; i++) {
        if (in_sizes[i] == BQ) t = (const float*)d_in[i];
        else if (in_sizes[i] == BQ * DD) x = (const float*)d_in[i];
        else if (in_sizes[i] == NS * DD) s = (const float*)d_in[i];
    }
    float* out = (float*)d_out;

    s2_kernel<<<NS / 8, 256>>>(s);

    cudaFuncSetAttribute(score_kernel, cudaFuncAttributeMaxDynamicSharedMemorySize,
                         SMEM_BYTES);
    score_kernel<<<BQ / BM, NTHREADS, SMEM_BYTES>>>(t, x, s, out);
}

// round 3
// speedup vs baseline: 2.1131x; 2.1131x over previous
#include <cuda_runtime.h>

#define BQ 4096
#define NS 8192
#define NSH (NS / 2)         // samples per half
#define DD 256
#define BM 64
#define BN 64
#define XST 260              // padded row stride (floats); 1040B, 16B-aligned, conflict-free phases
#define PST 72               // P tile stride: GEMM2 P reads conflict-free
#define NTHREADS 256
#define NTILES (NSH / BN)    // 64 tiles per half

#define SMEM_FLOATS (BM * XST + 2 * BN * XST + BM * PST + 5 * BM)
#define SMEM_BYTES (SMEM_FLOATS * 4)

__device__ float g_s2half[NS];
__device__ float g_m[2 * BQ];
__device__ float g_l[2 * BQ];
__device__ float g_O[2 * BQ * DD];

static __device__ __forceinline__ unsigned long long ffma2(unsigned long long a,
                                                           unsigned long long b,
                                                           unsigned long long c) {
    unsigned long long d;
    asm("fma.rn.f32x2 %0, %1, %2, %3;" : "=l"(d) : "l"(a), "l"(b), "l"(c));
    return d;
}
static __device__ __forceinline__ unsigned long long fmul2(unsigned long long a,
                                                           unsigned long long b) {
    unsigned long long d;
    asm("mul.rn.f32x2 %0, %1, %2;" : "=l"(d) : "l"(a), "l"(b));
    return d;
}
static __device__ __forceinline__ unsigned long long pk2(float lo, float hi) {
    unsigned long long r;
    asm("mov.b64 %0, {%1, %2};" : "=l"(r) : "f"(lo), "f"(hi));
    return r;
}
static __device__ __forceinline__ float lo2(unsigned long long v) {
    return __uint_as_float((unsigned)v);
}
static __device__ __forceinline__ float hi2(unsigned long long v) {
    return __uint_as_float((unsigned)(v >> 32));
}

#define CP_ASYNC16(dst_u32, src_ptr)                                        \
    asm volatile("cp.async.cg.shared.global [%0], [%1], 16;" ::"r"(dst_u32), \
                 "l"(src_ptr))
#define CP_COMMIT() asm volatile("cp.async.commit_group;" ::: "memory")
#define CP_WAIT1() asm volatile("cp.async.wait_group 1;" ::: "memory")

// 0.5 * ||s_n||^2, one warp per sample
__global__ void s2_kernel(const float* __restrict__ samples) {
    int w = (blockIdx.x * blockDim.x + threadIdx.x) >> 5;
    int lane = threadIdx.x & 31;
    if (w >= NS) return;
    const float* row = samples + (size_t)w * DD;
    float s = 0.f;
    #pragma unroll
    for (int i = 0; i < DD / 32; i++) {
        float v = row[lane + 32 * i];
        s = fmaf(v, v, s);
    }
    #pragma unroll
    for (int o = 16; o; o >>= 1) s += __shfl_xor_sync(0xffffffffu, s, o);
    if (lane == 0) g_s2half[w] = 0.5f * s;
}

__global__ __launch_bounds__(NTHREADS, 1) void score_part(
    const float* __restrict__ tvec, const float* __restrict__ x,
    const float* __restrict__ samples) {
    extern __shared__ float smem[];
    float* sX = smem;                      // BM x XST
    float* sK0 = sX + BM * XST;            // BN x XST (double buffered)
    float* sK1 = sK0 + BN * XST;
    float* sP = sK1 + BN * XST;            // BM x PST
    float* sInvd = sP + BM * PST;
    float* sM = sInvd + BM;
    float* sL = sM + BM;
    float* sAl = sL + BM;
    float* sS2 = sAl + BM;

    const int tid = threadIdx.x;
    const int qblk = blockIdx.x >> 1;
    const int h = blockIdx.x & 1;
    const int qbase = qblk * BM;
    const int nbase0 = h * NSH;

    const int ty = tid >> 4;  // 0..15 : query row group {ty, ty+16, ty+32, ty+48}
    const int tx = tid & 15;  // 0..15 : col group (GEMM1) / d-chunk (GEMM2)

    // ---- load X tile (64 x 256) ----
    #pragma unroll
    for (int r = 0; r < (BM * DD / 4) / NTHREADS; r++) {
        int idx = tid + NTHREADS * r;
        int row = idx >> 6, c4 = idx & 63;
        float4 v = *(const float4*)(x + (size_t)(qbase + row) * DD + c4 * 4);
        *(float4*)(sX + row * XST + c4 * 4) = v;
    }
    if (tid < BM) {
        float tt = tvec[qbase + tid];
        float ts = 0.01f * exp2f(tt * 13.287712379549449f);
        float dn = fmaf(ts, ts, 1e-8f);
        sInvd[tid] = 1.0f / dn;
        sM[tid] = __int_as_float(0xff800000);
        sL[tid] = 0.0f;
    }

    // prefetch K tile 0
    {
        unsigned int kdst = (unsigned int)__cvta_generic_to_shared(sK0);
        const float* gsrc = samples + (size_t)nbase0 * DD;
        #pragma unroll
        for (int r = 0; r < (BN * DD / 4) / NTHREADS; r++) {
            int idx = tid + NTHREADS * r;
            int row = idx >> 6, c4 = idx & 63;
            CP_ASYNC16(kdst + (row * XST + c4 * 4) * 4, gsrc + row * DD + c4 * 4);
        }
    }
    CP_COMMIT();

    unsigned long long O2[4][8];  // 4 rows x 16 floats (packed)
    #pragma unroll
    for (int i = 0; i < 4; i++)
        #pragma unroll
        for (int j = 0; j < 8; j++) O2[i][j] = 0ull;

    for (int kt = 0; kt < NTILES; kt++) {
        float* sKc = (kt & 1) ? sK1 : sK0;
        // prefetch next tile into the other buffer
        if (kt + 1 < NTILES) {
            float* sKn = (kt & 1) ? sK0 : sK1;
            unsigned int kdst = (unsigned int)__cvta_generic_to_shared(sKn);
            const float* gsrc = samples + (size_t)(nbase0 + (kt + 1) * BN) * DD;
            #pragma unroll
            for (int r = 0; r < (BN * DD / 4) / NTHREADS; r++) {
                int idx = tid + NTHREADS * r;
                int row = idx >> 6, c4 = idx & 63;
                CP_ASYNC16(kdst + (row * XST + c4 * 4) * 4, gsrc + row * DD + c4 * 4);
            }
        }
        CP_COMMIT();
        CP_WAIT1();
        if (tid < BN) sS2[tid] = g_s2half[nbase0 + kt * BN + tid];
        __syncthreads();

        // ---- GEMM1: S[4][4] = X @ K^T (4x4 micro-tile, packed f32x2) ----
        unsigned long long acc[16];
        #pragma unroll
        for (int j = 0; j < 16; j++) acc[j] = 0ull;
        {
            const ulonglong2* Xr[4];
            const ulonglong2* Kr[4];
            #pragma unroll
            for (int i = 0; i < 4; i++) {
                Xr[i] = (const ulonglong2*)(sX + (ty + 16 * i) * XST);
                Kr[i] = (const ulonglong2*)(sKc + (tx + 16 * i) * XST);
            }
            #pragma unroll 4
            for (int g = 0; g < DD / 4; g++) {
                ulonglong2 av[4], bv[4];
                #pragma unroll
                for (int i = 0; i < 4; i++) av[i] = Xr[i][g];
                #pragma unroll
                for (int i = 0; i < 4; i++) bv[i] = Kr[i][g];
                #pragma unroll
                for (int i = 0; i < 4; i++)
                    #pragma unroll
                    for (int j = 0; j < 4; j++) {
                        acc[i * 4 + j] = ffma2(av[i].x, bv[j].x, acc[i * 4 + j]);
                        acc[i * 4 + j] = ffma2(av[i].y, bv[j].y, acc[i * 4 + j]);
                    }
            }
        }

        // ---- online softmax (per thread: 4 rows x 4 cols) ----
        float s2c[4];
        #pragma unroll
        for (int j = 0; j < 4; j++) s2c[j] = sS2[tx + 16 * j];

        float al[4];
        #pragma unroll
        for (int i = 0; i < 4; i++) {
            int row = ty + 16 * i;
            float invd = sInvd[row];
            float lg[4];
            #pragma unroll
            for (int j = 0; j < 4; j++) {
                float dot = (lo2(acc[i * 4 + j]) + hi2(acc[i * 4 + j]));
                lg[j] = (dot - s2c[j]) * invd;
            }
            float rmax = fmaxf(fmaxf(lg[0], lg[1]), fmaxf(lg[2], lg[3]));
            #pragma unroll
            for (int o = 8; o; o >>= 1)
                rmax = fmaxf(rmax, __shfl_xor_sync(0xffffffffu, rmax, o));
            float mold = sM[row];
            float mnew = fmaxf(mold, rmax);
            float p0 = __expf(lg[0] - mnew), p1 = __expf(lg[1] - mnew);
            float p2 = __expf(lg[2] - mnew), p3 = __expf(lg[3] - mnew);
            float rs = (p0 + p1) + (p2 + p3);
            #pragma unroll
            for (int o = 8; o; o >>= 1) rs += __shfl_xor_sync(0xffffffffu, rs, o);
            sP[row * PST + tx] = p0;
            sP[row * PST + tx + 16] = p1;
            sP[row * PST + tx + 32] = p2;
            sP[row * PST + tx + 48] = p3;
            float a = __expf(mold - mnew);
            al[i] = a;
            if (tx == 0) {
                sM[row] = mnew;
                sL[row] = sL[row] * a + rs;
                sAl[row] = a;
            }
        }
        __syncthreads();

        // ---- GEMM2: O += P @ K (4 rows/thread share K loads) ----
        #pragma unroll
        for (int i = 0; i < 4; i++) {
            float a = al[i];  // own-warp row: register value is the true alpha
            if (a != 1.0f) {
                unsigned long long a2 = pk2(a, a);
                #pragma unroll
                for (int j = 0; j < 8; j++) O2[i][j] = fmul2(O2[i][j], a2);
            }
        }
        {
            const float* Pb = sP + ty * PST;
            #pragma unroll 2
            for (int k = 0; k < BN; k++) {
                const ulonglong2* Kr = (const ulonglong2*)(sKc + k * XST) + tx;
                ulonglong2 kv[4];
                #pragma unroll
                for (int j = 0; j < 4; j++) kv[j] = Kr[16 * j];
                #pragma unroll
                for (int i = 0; i < 4; i++) {
                    float p = Pb[16 * i * PST + k];
                    unsigned long long p2 = pk2(p, p);
                    #pragma unroll
                    for (int j = 0; j < 4; j++) {
                        O2[i][2 * j] = ffma2(p2, kv[j].x, O2[i][2 * j]);
                        O2[i][2 * j + 1] = ffma2(p2, kv[j].y, O2[i][2 * j + 1]);
                    }
                }
            }
        }
        __syncthreads();
    }

    // ---- store partials: unnormalized O, plus (m, l) per row ----
    #pragma unroll
    for (int i = 0; i < 4; i++) {
        int row = ty + 16 * i;
        int q = qbase + row;
        float* orow = g_O + ((size_t)h * BQ + q) * DD;
        #pragma unroll
        for (int j = 0; j < 4; j++) {
            float4 o;
            o.x = lo2(O2[i][2 * j]);
            o.y = hi2(O2[i][2 * j]);
            o.z = lo2(O2[i][2 * j + 1]);
            o.w = hi2(O2[i][2 * j + 1]);
            *(float4*)(orow + 4 * tx + 64 * j) = o;
        }
        if (tx == 0) {
            g_m[h * BQ + q] = sM[row];
            g_l[h * BQ + q] = sL[row];
        }
    }
}

// merge the two halves + epilogue
__global__ void combine_kernel(const float* __restrict__ tvec,
                               const float* __restrict__ x,
                               float* __restrict__ out) {
    int idx = blockIdx.x * blockDim.x + threadIdx.x;  // over BQ * 64 float4
    int q = idx >> 6, c4 = idx & 63;
    float m0 = g_m[q], m1 = g_m[BQ + q];
    float l0 = g_l[q], l1 = g_l[BQ + q];
    float m = fmaxf(m0, m1);
    float e0 = __expf(m0 - m), e1 = __expf(m1 - m);
    float linv = 1.0f / (l0 * e0 + l1 * e1);
    float w0 = e0 * linv, w1 = e1 * linv;

    float tt = tvec[q];
    float ts = 0.01f * exp2f(tt * 13.287712379549449f);
    float scale = ts / fmaf(ts, ts, 1e-8f);

    float4 o0 = *(const float4*)(g_O + (size_t)q * DD + c4 * 4);
    float4 o1 = *(const float4*)(g_O + ((size_t)BQ + q) * DD + c4 * 4);
    float4 xx = *(const float4*)(x + (size_t)q * DD + c4 * 4);
    float4 r;
    r.x = (o0.x * w0 + o1.x * w1 - xx.x) * scale;
    r.y = (o0.y * w0 + o1.y * w1 - xx.y) * scale;
    r.z = (o0.z * w0 + o1.z * w1 - xx.z) * scale;
    r.w = (o0.w * w0 + o1.w * w1 - xx.w) * scale;
    *(float4*)(out + (size_t)q * DD + c4 * 4) = r;
}

extern "C" void kernel_launch(void* const* d_in, const int* in_sizes, int n_in,
                              void* d_out, int out_size) {
    const float* t = nullptr;
    const float* x = nullptr;
    const float* s = nullptr;
    for (int i = 0; i < n_in; i++) {
        if (in_sizes[i] == BQ) t = (const float*)d_in[i];
        else if (in_sizes[i] == BQ * DD) x = (const float*)d_in[i];
        else if (in_sizes[i] == NS * DD) s = (const float*)d_in[i];
    }
    float* out = (float*)d_out;

    s2_kernel<<<NS / 8, 256>>>(s);

    cudaFuncSetAttribute(score_part, cudaFuncAttributeMaxDynamicSharedMemorySize,
                         SMEM_BYTES);
    score_part<<<(BQ / BM) * 2, NTHREADS, SMEM_BYTES>>>(t, x, s);

    combine_kernel<<<BQ * (DD / 4) / 256, 256>>>(t, x, out);
}

// round 4
// speedup vs baseline: 2.2286x; 1.0546x over previous
#include <cuda_runtime.h>

#define BQ 4096
#define NS 8192
#define NSH (NS / 2)         // samples per half
#define DD 256
#define BM 64
#define BN 64
#define XST 260              // padded row stride (floats); 1040B, 16B-aligned, conflict-free phases
#define PST 72               // P tile stride: GEMM2 P reads conflict-free
#define NTHREADS 256
#define NTILES (NSH / BN)    // 64 tiles per half

#define SMEM_FLOATS (BM * XST + 2 * BN * XST + BM * PST + 5 * BM)
#define SMEM_BYTES (SMEM_FLOATS * 4)

__device__ float g_s2half[NS];
__device__ float g_m[2 * BQ];
__device__ float g_l[2 * BQ];
__device__ float g_O[2 * BQ * DD];

static __device__ __forceinline__ unsigned long long ffma2(unsigned long long a,
                                                           unsigned long long b,
                                                           unsigned long long c) {
    unsigned long long d;
    asm("fma.rn.f32x2 %0, %1, %2, %3;" : "=l"(d) : "l"(a), "l"(b), "l"(c));
    return d;
}
static __device__ __forceinline__ unsigned long long fmul2(unsigned long long a,
                                                           unsigned long long b) {
    unsigned long long d;
    asm("mul.rn.f32x2 %0, %1, %2;" : "=l"(d) : "l"(a), "l"(b));
    return d;
}
static __device__ __forceinline__ unsigned long long pk2(float lo, float hi) {
    unsigned long long r;
    asm("mov.b64 %0, {%1, %2};" : "=l"(r) : "f"(lo), "f"(hi));
    return r;
}
static __device__ __forceinline__ float lo2(unsigned long long v) {
    return __uint_as_float((unsigned)v);
}
static __device__ __forceinline__ float hi2(unsigned long long v) {
    return __uint_as_float((unsigned)(v >> 32));
}

#define CP_ASYNC16(dst_u32, src_ptr)                                        \
    asm volatile("cp.async.cg.shared.global [%0], [%1], 16;" ::"r"(dst_u32), \
                 "l"(src_ptr))
#define CP_COMMIT() asm volatile("cp.async.commit_group;" ::: "memory")
#define CP_WAIT1() asm volatile("cp.async.wait_group 1;" ::: "memory")

// 0.5 * ||s_n||^2, one warp per sample
__global__ void s2_kernel(const float* __restrict__ samples) {
    int w = (blockIdx.x * blockDim.x + threadIdx.x) >> 5;
    int lane = threadIdx.x & 31;
    if (w >= NS) return;
    const float* row = samples + (size_t)w * DD;
    float s = 0.f;
    #pragma unroll
    for (int i = 0; i < DD / 32; i++) {
        float v = row[lane + 32 * i];
        s = fmaf(v, v, s);
    }
    #pragma unroll
    for (int o = 16; o; o >>= 1) s += __shfl_xor_sync(0xffffffffu, s, o);
    if (lane == 0) g_s2half[w] = 0.5f * s;
}

__global__ __launch_bounds__(NTHREADS, 1) void score_part(
    const float* __restrict__ tvec, const float* __restrict__ x,
    const float* __restrict__ samples) {
    extern __shared__ float smem[];
    float* sX = smem;                      // BM x XST
    float* sK0 = sX + BM * XST;            // BN x XST (double buffered)
    float* sK1 = sK0 + BN * XST;
    float* sP = sK1 + BN * XST;            // BM x PST
    float* sInvd = sP + BM * PST;
    float* sM = sInvd + BM;
    float* sL = sM + BM;
    float* sAl = sL + BM;
    float* sS2 = sAl + BM;

    const int tid = threadIdx.x;
    const int qblk = blockIdx.x >> 1;
    const int h = blockIdx.x & 1;
    const int qbase = qblk * BM;
    const int nbase0 = h * NSH;

    const int ty = tid >> 4;  // 0..15 : query row group {ty, ty+16, ty+32, ty+48}
    const int tx = tid & 15;  // 0..15 : col group (GEMM1) / d-chunk (GEMM2)

    // ---- load X tile (64 x 256) ----
    #pragma unroll
    for (int r = 0; r < (BM * DD / 4) / NTHREADS; r++) {
        int idx = tid + NTHREADS * r;
        int row = idx >> 6, c4 = idx & 63;
        float4 v = *(const float4*)(x + (size_t)(qbase + row) * DD + c4 * 4);
        *(float4*)(sX + row * XST + c4 * 4) = v;
    }
    if (tid < BM) {
        float tt = tvec[qbase + tid];
        float ts = 0.01f * exp2f(tt * 13.287712379549449f);
        float dn = fmaf(ts, ts, 1e-8f);
        sInvd[tid] = 1.0f / dn;
        sM[tid] = __int_as_float(0xff800000);
        sL[tid] = 0.0f;
    }

    // prefetch K tile 0
    {
        unsigned int kdst = (unsigned int)__cvta_generic_to_shared(sK0);
        const float* gsrc = samples + (size_t)nbase0 * DD;
        #pragma unroll
        for (int r = 0; r < (BN * DD / 4) / NTHREADS; r++) {
            int idx = tid + NTHREADS * r;
            int row = idx >> 6, c4 = idx & 63;
            CP_ASYNC16(kdst + (row * XST + c4 * 4) * 4, gsrc + row * DD + c4 * 4);
        }
    }
    CP_COMMIT();

    unsigned long long O2[4][8];  // 4 rows x 16 floats (packed)
    #pragma unroll
    for (int i = 0; i < 4; i++)
        #pragma unroll
        for (int j = 0; j < 8; j++) O2[i][j] = 0ull;

    for (int kt = 0; kt < NTILES; kt++) {
        float* sKc = (kt & 1) ? sK1 : sK0;
        // prefetch next tile into the other buffer
        if (kt + 1 < NTILES) {
            float* sKn = (kt & 1) ? sK0 : sK1;
            unsigned int kdst = (unsigned int)__cvta_generic_to_shared(sKn);
            const float* gsrc = samples + (size_t)(nbase0 + (kt + 1) * BN) * DD;
            #pragma unroll
            for (int r = 0; r < (BN * DD / 4) / NTHREADS; r++) {
                int idx = tid + NTHREADS * r;
                int row = idx >> 6, c4 = idx & 63;
                CP_ASYNC16(kdst + (row * XST + c4 * 4) * 4, gsrc + row * DD + c4 * 4);
            }
        }
        CP_COMMIT();
        CP_WAIT1();
        if (tid < BN) sS2[tid] = g_s2half[nbase0 + kt * BN + tid];
        __syncthreads();

        // ---- GEMM1: S[4][4] = X @ K^T (4x4 micro-tile, packed f32x2) ----
        unsigned long long acc[16];
        #pragma unroll
        for (int j = 0; j < 16; j++) acc[j] = 0ull;
        {
            const ulonglong2* Xr[4];
            const ulonglong2* Kr[4];
            #pragma unroll
            for (int i = 0; i < 4; i++) {
                Xr[i] = (const ulonglong2*)(sX + (ty + 16 * i) * XST);
                Kr[i] = (const ulonglong2*)(sKc + (tx + 16 * i) * XST);
            }
            #pragma unroll 4
            for (int g = 0; g < DD / 4; g++) {
                ulonglong2 av[4], bv[4];
                #pragma unroll
                for (int i = 0; i < 4; i++) av[i] = Xr[i][g];
                #pragma unroll
                for (int i = 0; i < 4; i++) bv[i] = Kr[i][g];
                #pragma unroll
                for (int i = 0; i < 4; i++)
                    #pragma unroll
                    for (int j = 0; j < 4; j++) {
                        acc[i * 4 + j] = ffma2(av[i].x, bv[j].x, acc[i * 4 + j]);
                        acc[i * 4 + j] = ffma2(av[i].y, bv[j].y, acc[i * 4 + j]);
                    }
            }
        }

        // ---- online softmax (per thread: 4 rows x 4 cols) ----
        float s2c[4];
        #pragma unroll
        for (int j = 0; j < 4; j++) s2c[j] = sS2[tx + 16 * j];

        float al[4];
        #pragma unroll
        for (int i = 0; i < 4; i++) {
            int row = ty + 16 * i;
            float invd = sInvd[row];
            float lg[4];
            #pragma unroll
            for (int j = 0; j < 4; j++) {
                float dot = (lo2(acc[i * 4 + j]) + hi2(acc[i * 4 + j]));
                lg[j] = (dot - s2c[j]) * invd;
            }
            float rmax = fmaxf(fmaxf(lg[0], lg[1]), fmaxf(lg[2], lg[3]));
            #pragma unroll
            for (int o = 8; o; o >>= 1)
                rmax = fmaxf(rmax, __shfl_xor_sync(0xffffffffu, rmax, o));
            float mold = sM[row];
            float mnew = fmaxf(mold, rmax);
            float p0 = __expf(lg[0] - mnew), p1 = __expf(lg[1] - mnew);
            float p2 = __expf(lg[2] - mnew), p3 = __expf(lg[3] - mnew);
            float rs = (p0 + p1) + (p2 + p3);
            #pragma unroll
            for (int o = 8; o; o >>= 1) rs += __shfl_xor_sync(0xffffffffu, rs, o);
            sP[row * PST + tx] = p0;
            sP[row * PST + tx + 16] = p1;
            sP[row * PST + tx + 32] = p2;
            sP[row * PST + tx + 48] = p3;
            float a = __expf(mold - mnew);
            al[i] = a;
            if (tx == 0) {
                sM[row] = mnew;
                sL[row] = sL[row] * a + rs;
                sAl[row] = a;
            }
        }
        __syncthreads();

        // ---- GEMM2: O += P @ K (4 rows/thread share K loads) ----
        #pragma unroll
        for (int i = 0; i < 4; i++) {
            float a = al[i];  // own-warp row: register value is the true alpha
            if (a != 1.0f) {
                unsigned long long a2 = pk2(a, a);
                #pragma unroll
                for (int j = 0; j < 8; j++) O2[i][j] = fmul2(O2[i][j], a2);
            }
        }
        {
            const float* Pb = sP + ty * PST;
            #pragma unroll 2
            for (int k = 0; k < BN; k++) {
                const ulonglong2* Kr = (const ulonglong2*)(sKc + k * XST) + tx;
                ulonglong2 kv[4];
                #pragma unroll
                for (int j = 0; j < 4; j++) kv[j] = Kr[16 * j];
                #pragma unroll
                for (int i = 0; i < 4; i++) {
                    float p = Pb[16 * i * PST + k];
                    unsigned long long p2 = pk2(p, p);
                    #pragma unroll
                    for (int j = 0; j < 4; j++) {
                        O2[i][2 * j] = ffma2(p2, kv[j].x, O2[i][2 * j]);
                        O2[i][2 * j + 1] = ffma2(p2, kv[j].y, O2[i][2 * j + 1]);
                    }
                }
            }
        }
        __syncthreads();
    }

    // ---- store partials: unnormalized O, plus (m, l) per row ----
    #pragma unroll
    for (int i = 0; i < 4; i++) {
        int row = ty + 16 * i;
        int q = qbase + row;
        float* orow = g_O + ((size_t)h * BQ + q) * DD;
        #pragma unroll
        for (int j = 0; j < 4; j++) {
            float4 o;
            o.x = lo2(O2[i][2 * j]);
            o.y = hi2(O2[i][2 * j]);
            o.z = lo2(O2[i][2 * j + 1]);
            o.w = hi2(O2[i][2 * j + 1]);
            *(float4*)(orow + 4 * tx + 64 * j) = o;
        }
        if (tx == 0) {
            g_m[h * BQ + q] = sM[row];
            g_l[h * BQ + q] = sL[row];
        }
    }
}

// merge the two halves + epilogue
__global__ void combine_kernel(const float* __restrict__ tvec,
                               const float* __restrict__ x,
                               float* __restrict__ out) {
    int idx = blockIdx.x * blockDim.x + threadIdx.x;  // over BQ * 64 float4
    int q = idx >> 6, c4 = idx & 63;
    float m0 = g_m[q], m1 = g_m[BQ + q];
    float l0 = g_l[q], l1 = g_l[BQ + q];
    float m = fmaxf(m0, m1);
    float e0 = __expf(m0 - m), e1 = __expf(m1 - m);
    float linv = 1.0f / (l0 * e0 + l1 * e1);
    float w0 = e0 * linv, w1 = e1 * linv;

    float tt = tvec[q];
    float ts = 0.01f * exp2f(tt * 13.287712379549449f);
    float scale = ts / fmaf(ts, ts, 1e-8f);

    float4 o0 = *(const float4*)(g_O + (size_t)q * DD + c4 * 4);
    float4 o1 = *(const float4*)(g_O + ((size_t)BQ + q) * DD + c4 * 4);
    float4 xx = *(const float4*)(x + (size_t)q * DD + c4 * 4);
    float4 r;
    r.x = (o0.x * w0 + o1.x * w1 - xx.x) * scale;
    r.y = (o0.y * w0 + o1.y * w1 - xx.y) * scale;
    r.z = (o0.z * w0 + o1.z * w1 - xx.z) * scale;
    r.w = (o0.w * w0 + o1.w * w1 - xx.w) * scale;
    *(float4*)(out + (size_t)q * DD + c4 * 4) = r;
}

extern "C" void kernel_launch(void* const* d_in, const int* in_sizes, int n_in,
                              void* d_out, int out_size) {
    const float* t = nullptr;
    const float* x = nullptr;
    const float* s = nullptr;
    for (int i = 0; i < n_in; i++) {
        if (in_sizes[i] == BQ) t = (const float*)d_in[i];
        else if (in_sizes[i] == BQ * DD) x = (const float*)d_in[i];
        else if (in_sizes[i] == NS * DD) s = (const float*)d_in[i];
    }
    float* out = (float*)d_out;

    s2_kernel<<<NS / 8, 256>>>(s);

    cudaFuncSetAttribute(score_part, cudaFuncAttributeMaxDynamicSharedMemorySize,
                         SMEM_BYTES);
    score_part<<<(BQ / BM) * 2, NTHREADS, SMEM_BYTES>>>(t, x, s);

    combine_kernel<<<BQ * (DD / 4) / 256, 256>>>(t, x, out);
}

// round 5
// speedup vs baseline: 2.2336x; 1.0022x over previous
#include <cuda_runtime.h>

#define BQ 4096
#define NS 8192
#define NSH (NS / 2)         // samples per half
#define DD 256
#define BM 64
#define BN 64
#define XST 260              // padded row stride (floats); 1040B, 16B-aligned, conflict-free phases
#define PST 72               // P tile stride: GEMM2 P reads conflict-free
#define NTHREADS 256
#define NTILES (NSH / BN)    // 64 tiles per half

#define SMEM_FLOATS (BM * XST + 2 * BN * XST + BM * PST + 5 * BM)
#define SMEM_BYTES (SMEM_FLOATS * 4)

__device__ float g_s2half[NS];
__device__ float g_m[2 * BQ];
__device__ float g_l[2 * BQ];
__device__ float g_O[2 * BQ * DD];

static __device__ __forceinline__ unsigned long long ffma2(unsigned long long a,
                                                           unsigned long long b,
                                                           unsigned long long c) {
    unsigned long long d;
    asm("fma.rn.f32x2 %0, %1, %2, %3;" : "=l"(d) : "l"(a), "l"(b), "l"(c));
    return d;
}
static __device__ __forceinline__ unsigned long long fmul2(unsigned long long a,
                                                           unsigned long long b) {
    unsigned long long d;
    asm("mul.rn.f32x2 %0, %1, %2;" : "=l"(d) : "l"(a), "l"(b));
    return d;
}
static __device__ __forceinline__ unsigned long long pk2(float lo, float hi) {
    unsigned long long r;
    asm("mov.b64 %0, {%1, %2};" : "=l"(r) : "f"(lo), "f"(hi));
    return r;
}
static __device__ __forceinline__ float lo2(unsigned long long v) {
    return __uint_as_float((unsigned)v);
}
static __device__ __forceinline__ float hi2(unsigned long long v) {
    return __uint_as_float((unsigned)(v >> 32));
}

#define CP_ASYNC16(dst_u32, src_ptr)                                        \
    asm volatile("cp.async.cg.shared.global [%0], [%1], 16;" ::"r"(dst_u32), \
                 "l"(src_ptr))
#define CP_COMMIT() asm volatile("cp.async.commit_group;" ::: "memory")
#define CP_WAIT1() asm volatile("cp.async.wait_group 1;" ::: "memory")

// 0.5 * ||s_n||^2, one warp per sample
__global__ void s2_kernel(const float* __restrict__ samples) {
    int w = (blockIdx.x * blockDim.x + threadIdx.x) >> 5;
    int lane = threadIdx.x & 31;
    if (w >= NS) return;
    const float* row = samples + (size_t)w * DD;
    float s = 0.f;
    #pragma unroll
    for (int i = 0; i < DD / 32; i++) {
        float v = row[lane + 32 * i];
        s = fmaf(v, v, s);
    }
    #pragma unroll
    for (int o = 16; o; o >>= 1) s += __shfl_xor_sync(0xffffffffu, s, o);
    if (lane == 0) g_s2half[w] = 0.5f * s;
}

__global__ __launch_bounds__(NTHREADS, 1) void score_part(
    const float* __restrict__ tvec, const float* __restrict__ x,
    const float* __restrict__ samples) {
    extern __shared__ float smem[];
    float* sX = smem;                      // BM x XST
    float* sK0 = sX + BM * XST;            // BN x XST (double buffered)
    float* sK1 = sK0 + BN * XST;
    float* sP = sK1 + BN * XST;            // BM x PST
    float* sInvd = sP + BM * PST;
    float* sM = sInvd + BM;
    float* sL = sM + BM;
    float* sAl = sL + BM;
    float* sS2 = sAl + BM;

    const int tid = threadIdx.x;
    const int qblk = blockIdx.x >> 1;
    const int h = blockIdx.x & 1;
    const int qbase = qblk * BM;
    const int nbase0 = h * NSH;

    const int ty = tid >> 4;  // 0..15 : query row group {ty, ty+16, ty+32, ty+48}
    const int tx = tid & 15;  // 0..15 : col group (GEMM1) / d-chunk (GEMM2)

    // ---- load X tile (64 x 256) ----
    #pragma unroll
    for (int r = 0; r < (BM * DD / 4) / NTHREADS; r++) {
        int idx = tid + NTHREADS * r;
        int row = idx >> 6, c4 = idx & 63;
        float4 v = *(const float4*)(x + (size_t)(qbase + row) * DD + c4 * 4);
        *(float4*)(sX + row * XST + c4 * 4) = v;
    }
    if (tid < BM) {
        float tt = tvec[qbase + tid];
        float ts = 0.01f * exp2f(tt * 13.287712379549449f);
        float dn = fmaf(ts, ts, 1e-8f);
        sInvd[tid] = 1.0f / dn;
        sM[tid] = __int_as_float(0xff800000);
        sL[tid] = 0.0f;
    }

    // prefetch K tile 0
    {
        unsigned int kdst = (unsigned int)__cvta_generic_to_shared(sK0);
        const float* gsrc = samples + (size_t)nbase0 * DD;
        #pragma unroll
        for (int r = 0; r < (BN * DD / 4) / NTHREADS; r++) {
            int idx = tid + NTHREADS * r;
            int row = idx >> 6, c4 = idx & 63;
            CP_ASYNC16(kdst + (row * XST + c4 * 4) * 4, gsrc + row * DD + c4 * 4);
        }
    }
    CP_COMMIT();

    unsigned long long O2[4][8];  // 4 rows x 16 floats (packed)
    #pragma unroll
    for (int i = 0; i < 4; i++)
        #pragma unroll
        for (int j = 0; j < 8; j++) O2[i][j] = 0ull;

    for (int kt = 0; kt < NTILES; kt++) {
        float* sKc = (kt & 1) ? sK1 : sK0;
        // prefetch next tile into the other buffer
        if (kt + 1 < NTILES) {
            float* sKn = (kt & 1) ? sK0 : sK1;
            unsigned int kdst = (unsigned int)__cvta_generic_to_shared(sKn);
            const float* gsrc = samples + (size_t)(nbase0 + (kt + 1) * BN) * DD;
            #pragma unroll
            for (int r = 0; r < (BN * DD / 4) / NTHREADS; r++) {
                int idx = tid + NTHREADS * r;
                int row = idx >> 6, c4 = idx & 63;
                CP_ASYNC16(kdst + (row * XST + c4 * 4) * 4, gsrc + row * DD + c4 * 4);
            }
        }
        CP_COMMIT();
        CP_WAIT1();
        if (tid < BN) sS2[tid] = g_s2half[nbase0 + kt * BN + tid];
        __syncthreads();

        // ---- GEMM1: S[4][4] = X @ K^T (4x4 micro-tile, packed f32x2) ----
        unsigned long long acc[16];
        #pragma unroll
        for (int j = 0; j < 16; j++) acc[j] = 0ull;
        {
            const ulonglong2* Xr[4];
            const ulonglong2* Kr[4];
            #pragma unroll
            for (int i = 0; i < 4; i++) {
                Xr[i] = (const ulonglong2*)(sX + (ty + 16 * i) * XST);
                Kr[i] = (const ulonglong2*)(sKc + (tx + 16 * i) * XST);
            }
            #pragma unroll 4
            for (int g = 0; g < DD / 4; g++) {
                ulonglong2 av[4], bv[4];
                #pragma unroll
                for (int i = 0; i < 4; i++) av[i] = Xr[i][g];
                #pragma unroll
                for (int i = 0; i < 4; i++) bv[i] = Kr[i][g];
                #pragma unroll
                for (int i = 0; i < 4; i++)
                    #pragma unroll
                    for (int j = 0; j < 4; j++) {
                        acc[i * 4 + j] = ffma2(av[i].x, bv[j].x, acc[i * 4 + j]);
                        acc[i * 4 + j] = ffma2(av[i].y, bv[j].y, acc[i * 4 + j]);
                    }
            }
        }

        // ---- online softmax (per thread: 4 rows x 4 cols) ----
        float s2c[4];
        #pragma unroll
        for (int j = 0; j < 4; j++) s2c[j] = sS2[tx + 16 * j];

        float al[4];
        #pragma unroll
        for (int i = 0; i < 4; i++) {
            int row = ty + 16 * i;
            float invd = sInvd[row];
            float lg[4];
            #pragma unroll
            for (int j = 0; j < 4; j++) {
                float dot = (lo2(acc[i * 4 + j]) + hi2(acc[i * 4 + j]));
                lg[j] = (dot - s2c[j]) * invd;
            }
            float rmax = fmaxf(fmaxf(lg[0], lg[1]), fmaxf(lg[2], lg[3]));
            #pragma unroll
            for (int o = 8; o; o >>= 1)
                rmax = fmaxf(rmax, __shfl_xor_sync(0xffffffffu, rmax, o));
            float mold = sM[row];
            float mnew = fmaxf(mold, rmax);
            float p0 = __expf(lg[0] - mnew), p1 = __expf(lg[1] - mnew);
            float p2 = __expf(lg[2] - mnew), p3 = __expf(lg[3] - mnew);
            float rs = (p0 + p1) + (p2 + p3);
            #pragma unroll
            for (int o = 8; o; o >>= 1) rs += __shfl_xor_sync(0xffffffffu, rs, o);
            sP[row * PST + tx] = p0;
            sP[row * PST + tx + 16] = p1;
            sP[row * PST + tx + 32] = p2;
            sP[row * PST + tx + 48] = p3;
            float a = __expf(mold - mnew);
            al[i] = a;
            if (tx == 0) {
                sM[row] = mnew;
                sL[row] = sL[row] * a + rs;
                sAl[row] = a;
            }
        }
        __syncthreads();

        // ---- GEMM2: O += P @ K (4 rows/thread share K loads) ----
        #pragma unroll
        for (int i = 0; i < 4; i++) {
            float a = al[i];  // own-warp row: register value is the true alpha
            if (a != 1.0f) {
                unsigned long long a2 = pk2(a, a);
                #pragma unroll
                for (int j = 0; j < 8; j++) O2[i][j] = fmul2(O2[i][j], a2);
            }
        }
        {
            const float* Pb = sP + ty * PST;
            #pragma unroll 2
            for (int k = 0; k < BN; k++) {
                const ulonglong2* Kr = (const ulonglong2*)(sKc + k * XST) + tx;
                ulonglong2 kv[4];
                #pragma unroll
                for (int j = 0; j < 4; j++) kv[j] = Kr[16 * j];
                #pragma unroll
                for (int i = 0; i < 4; i++) {
                    float p = Pb[16 * i * PST + k];
                    unsigned long long p2 = pk2(p, p);
                    #pragma unroll
                    for (int j = 0; j < 4; j++) {
                        O2[i][2 * j] = ffma2(p2, kv[j].x, O2[i][2 * j]);
                        O2[i][2 * j + 1] = ffma2(p2, kv[j].y, O2[i][2 * j + 1]);
                    }
                }
            }
        }
        __syncthreads();
    }

    // ---- store partials: unnormalized O, plus (m, l) per row ----
    #pragma unroll
    for (int i = 0; i < 4; i++) {
        int row = ty + 16 * i;
        int q = qbase + row;
        float* orow = g_O + ((size_t)h * BQ + q) * DD;
        #pragma unroll
        for (int j = 0; j < 4; j++) {
            float4 o;
            o.x = lo2(O2[i][2 * j]);
            o.y = hi2(O2[i][2 * j]);
            o.z = lo2(O2[i][2 * j + 1]);
            o.w = hi2(O2[i][2 * j + 1]);
            *(float4*)(orow + 4 * tx + 64 * j) = o;
        }
        if (tx == 0) {
            g_m[h * BQ + q] = sM[row];
            g_l[h * BQ + q] = sL[row];
        }
    }
}

// merge the two halves + epilogue
__global__ void combine_kernel(const float* __restrict__ tvec,
                               const float* __restrict__ x,
                               float* __restrict__ out) {
    int idx = blockIdx.x * blockDim.x + threadIdx.x;  // over BQ * 64 float4
    int q = idx >> 6, c4 = idx & 63;
    float m0 = g_m[q], m1 = g_m[BQ + q];
    float l0 = g_l[q], l1 = g_l[BQ + q];
    float m = fmaxf(m0, m1);
    float e0 = __expf(m0 - m), e1 = __expf(m1 - m);
    float linv = 1.0f / (l0 * e0 + l1 * e1);
    float w0 = e0 * linv, w1 = e1 * linv;

    float tt = tvec[q];
    float ts = 0.01f * exp2f(tt * 13.287712379549449f);
    float scale = ts / fmaf(ts, ts, 1e-8f);

    float4 o0 = *(const float4*)(g_O + (size_t)q * DD + c4 * 4);
    float4 o1 = *(const float4*)(g_O + ((size_t)BQ + q) * DD + c4 * 4);
    float4 xx = *(const float4*)(x + (size_t)q * DD + c4 * 4);
    float4 r;
    r.x = (o0.x * w0 + o1.x * w1 - xx.x) * scale;
    r.y = (o0.y * w0 + o1.y * w1 - xx.y) * scale;
    r.z = (o0.z * w0 + o1.z * w1 - xx.z) * scale;
    r.w = (o0.w * w0 + o1.w * w1 - xx.w) * scale;
    *(float4*)(out + (size_t)q * DD + c4 * 4) = r;
}

extern "C" void kernel_launch(void* const* d_in, const int* in_sizes, int n_in,
                              void* d_out, int out_size) {
    const float* t = nullptr;
    const float* x = nullptr;
    const float* s = nullptr;
    for (int i = 0; i < n_in; i++) {
        if (in_sizes[i] == BQ) t = (const float*)d_in[i];
        else if (in_sizes[i] == BQ * DD) x = (const float*)d_in[i];
        else if (in_sizes[i] == NS * DD) s = (const float*)d_in[i];
    }
    float* out = (float*)d_out;

    s2_kernel<<<NS / 8, 256>>>(s);

    cudaFuncSetAttribute(score_part, cudaFuncAttributeMaxDynamicSharedMemorySize,
                         SMEM_BYTES);
    score_part<<<(BQ / BM) * 2, NTHREADS, SMEM_BYTES>>>(t, x, s);

    combine_kernel<<<BQ * (DD / 4) / 256, 256>>>(t, x, out);
}